// round 15
// baseline (speedup 1.0000x reference)
#include <cuda_runtime.h>
#include <cuda_bf16.h>
#include <cuda_fp16.h>
#include <cstdint>
#include <math.h>

#define BB 8
#define CC 512
#define LLEN 2048
#define NGRP 8
#define CPG 64
#define CL (CC*LLEN)
#define CC2 (CC*CC)
typedef unsigned short u16;

// ---------------- scratch ----------------
__device__ u16 g_hT[(size_t)BB*CL];          // hT [B][L][C] fp16
__device__ u16 g_h [(size_t)BB*CL];          // h  [B][C][L] fp16
__device__ u16 g_hp[(size_t)BB*CL];          // h'T = (M h)T [B][L][C]
__device__ u16 g_g [(size_t)BB*CL];          // gT = (P h)T [B][L][C]
__device__ u16 g_s [(size_t)BB*LLEN*LLEN];   // E = exp(S) [B][L][L]
__device__ u16 g_wA[2*CC2];                  // {wqT, wo} fp16
__device__ u16 g_wB[2*CC2];                  // {wkT, wvT} fp16
__device__ u16 g_wM[2*CC2];                  // {M=WqT*Wk, Wov=Wo*Wv} fp16
__device__ float g_u [CC];                   // WkT * bq
__device__ float g_bp[CC];                   // Wo*bv + bo
__device__ float g_cv[BB*LLEN];              // c_j per (b,j), pre-scaled
__device__ float g_rsum[BB*LLEN];            // row sums of exp(S)
__device__ float2 g_part[512];               // GN partial (sum, sumsq)

// ---------------- helpers ----------------
__device__ __forceinline__ uint32_t smem_u32(const void* p){
    uint32_t a;
    asm("{ .reg .u64 t; cvta.to.shared.u64 t, %1; cvt.u32.u64 %0, t; }" : "=r"(a) : "l"(p));
    return a;
}
__device__ __forceinline__ void cp16(uint32_t s, const void* g){
    asm volatile("cp.async.cg.shared.global [%0], [%1], 16;" :: "r"(s), "l"(g));
}
#define CP_COMMIT() asm volatile("cp.async.commit_group;" ::: "memory")
#define CP_WAIT1()  asm volatile("cp.async.wait_group 1;" ::: "memory")
#define CP_WAIT0()  asm volatile("cp.async.wait_group 0;" ::: "memory")

#define LDX4(r0,r1,r2,r3,addr) \
    asm volatile("ldmatrix.sync.aligned.m8n8.x4.shared.b16 {%0,%1,%2,%3}, [%4];" \
        : "=r"(r0), "=r"(r1), "=r"(r2), "=r"(r3) : "r"(addr))

#define MMA_F16(d, a, b) \
    asm volatile("mma.sync.aligned.m16n8k16.row.col.f32.f16.f16.f32 " \
        "{%0,%1,%2,%3}, {%4,%5,%6,%7}, {%8,%9}, {%0,%1,%2,%3};" \
        : "+f"((d)[0]), "+f"((d)[1]), "+f"((d)[2]), "+f"((d)[3]) \
        : "r"((a)[0]), "r"((a)[1]), "r"((a)[2]), "r"((a)[3]), "r"((b)[0]), "r"((b)[1]))

__device__ __forceinline__ uint32_t pack_h2(float v0, float v1){
    __half2 h = __floats2half2_rn(v0, v1);
    return *(uint32_t*)&h;
}

// ---------------- templated fp16 HMMA GEMM ----------------
// tile 128x128, 256 thr (8 warps of 64x32), BK=64, 3-stage, 2 CTA/SM (16 warps/SM)
#define F_OUTF32 1
#define F_RESID  4
#define F_BIASN  8
#define F_EXP    16
#define F_RINV   32
#define F_BIASM  64
#define OFF_A 0
#define OFF_B 16384
#define STG_B 32768
#define NSTAGE 3
#define DYN_SMEM (NSTAGE*STG_B + 128)

template<int MODE>
__global__ void __launch_bounds__(256, 2)
hmma_gemm(const u16* __restrict__ A, const u16* __restrict__ B,
          int K, int lda, int ldb, int ldc, long sA, long sB, long sC,
          float* __restrict__ Cf, u16* __restrict__ Ch,
          const float* __restrict__ biasM, const float* __restrict__ biasN, long sBN,
          const float* __restrict__ resid,
          float* __restrict__ rsum, const float* __restrict__ rinv, long sRow,
          float scale)
{
    extern __shared__ char dsm[];
    const uint32_t sbase = (smem_u32(dsm) + 127u) & ~127u;
    const int tid = threadIdx.x, lane = tid & 31, wid = tid >> 5;
    const int warpM = (wid & 1) * 64, warpN = (wid >> 1) * 32;
    const int bz = blockIdx.z;
    A += (size_t)bz * sA;
    B += (size_t)bz * sB;
    if (MODE & F_OUTF32) Cf += (size_t)bz * sC; else Ch += (size_t)bz * sC;
    if (MODE & F_RESID)  resid += (size_t)bz * sC;
    if (MODE & F_BIASN)  biasN += (size_t)bz * sBN;
    if (MODE & F_EXP)    rsum  += (size_t)bz * sRow;
    if (MODE & F_RINV)   rinv  += (size_t)bz * sRow;
    const int m0 = blockIdx.y * 128, n0 = blockIdx.x * 128;
    const int niter = K >> 6;

    const int c_row = tid >> 3, c_seg = tid & 7;   // 32 rows x 8 segs
    const uint32_t c_cb = (uint32_t)(c_seg * 16);

    auto issue = [&](int kt){
        const int kk = kt * 64;
        const uint32_t sb = sbase + (kt % NSTAGE) * STG_B;
        #pragma unroll
        for (int j = 0; j < 4; j++){
            const int row = c_row + j * 32;
            const uint32_t sw = (uint32_t)((row & 7) << 4);
            cp16(sb + OFF_A + row * 128 + (c_cb ^ sw),
                 A + (size_t)(m0 + row) * lda + kk + c_seg * 8);
        }
        #pragma unroll
        for (int j = 0; j < 4; j++){
            const int row = c_row + j * 32;
            const uint32_t sw = (uint32_t)((row & 7) << 4);
            cp16(sb + OFF_B + row * 128 + (c_cb ^ sw),
                 B + (size_t)(n0 + row) * ldb + kk + c_seg * 8);
        }
        CP_COMMIT();
    };

    float acc[4][4][4];
    #pragma unroll
    for (int i = 0; i < 4; i++)
        #pragma unroll
        for (int j = 0; j < 4; j++)
            #pragma unroll
            for (int t = 0; t < 4; t++) acc[i][j][t] = 0.f;

    const int aRow0 = warpM + (lane & 15);
    const uint32_t aSw = (uint32_t)((aRow0 & 7) << 4);
    const uint32_t aC  = (uint32_t)((lane >> 4) << 4);
    const int bRow0 = warpN + ((lane >> 4) << 3) + (lane & 7);
    const uint32_t bSw = (uint32_t)((bRow0 & 7) << 4);
    const uint32_t bC  = (uint32_t)(((lane >> 3) & 1) << 4);

    issue(0); if (niter > 1) issue(1);

    for (int kt = 0; kt < niter; kt++){
        if (kt + 1 < niter) CP_WAIT1(); else CP_WAIT0();
        __syncthreads();
        if (kt + 2 < niter) issue(kt + 2);
        const uint32_t sb = sbase + (kt % NSTAGE) * STG_B;

        #pragma unroll
        for (int ko = 0; ko < 4; ko++){
            const uint32_t kb = (uint32_t)(ko * 32);
            uint32_t a_f[4][4], b_f[2][4];
            #pragma unroll
            for (int p = 0; p < 2; p++){
                uint32_t bd = sb + OFF_B + (uint32_t)((bRow0 + p*16) * 128) + ((kb + bC) ^ bSw);
                LDX4(b_f[p][0], b_f[p][1], b_f[p][2], b_f[p][3], bd);
            }
            #pragma unroll
            for (int mt = 0; mt < 4; mt++){
                uint32_t ad = sb + OFF_A + (uint32_t)((aRow0 + mt*16) * 128) + ((kb + aC) ^ aSw);
                LDX4(a_f[mt][0], a_f[mt][1], a_f[mt][2], a_f[mt][3], ad);
            }
            #pragma unroll
            for (int mt = 0; mt < 4; mt++)
                #pragma unroll
                for (int nt = 0; nt < 4; nt++)
                    MMA_F16(acc[mt][nt], a_f[mt], &b_f[nt >> 1][(nt & 1) * 2]);
        }
        // no bottom barrier: prefetch distance 2 of 3 stages + top barrier order stage reuse
    }

    // ---- epilogue (compile-time specialized) ----
    #pragma unroll
    for (int mt = 0; mt < 4; mt++){
        const int r0 = m0 + warpM + mt * 16 + (lane >> 2);
        const int r1 = r0 + 8;
        float bm0 = 0.f, bm1 = 0.f;
        if (MODE & F_BIASM){ bm0 = biasM[r0]; bm1 = biasM[r1]; }
        float sc0 = 1.f, sc1 = 1.f;
        if (MODE & F_RINV){ sc0 = 1.f / rinv[r0]; sc1 = 1.f / rinv[r1]; }
        float sum0 = 0.f, sum1 = 0.f;
        #pragma unroll
        for (int nt = 0; nt < 4; nt++){
            const int c = n0 + warpN + nt * 8 + ((lane & 3) << 1);
            float v0 = acc[mt][nt][0] * scale + bm0;
            float v1 = acc[mt][nt][1] * scale + bm0;
            float v2 = acc[mt][nt][2] * scale + bm1;
            float v3 = acc[mt][nt][3] * scale + bm1;
            if (MODE & F_RINV){ v0 *= sc0; v1 *= sc0; v2 *= sc1; v3 *= sc1; }
            if (MODE & F_BIASN){
                float2 bn = *(const float2*)&biasN[c];
                v0 += bn.x; v1 += bn.y; v2 += bn.x; v3 += bn.y;
            }
            const size_t o0 = (size_t)r0 * ldc + c;
            const size_t o1 = (size_t)r1 * ldc + c;
            if (MODE & F_RESID){
                float2 x0 = *(const float2*)&resid[o0];
                float2 x1 = *(const float2*)&resid[o1];
                v0 += x0.x; v1 += x0.y; v2 += x1.x; v3 += x1.y;
            }
            if (MODE & F_EXP){
                v0 = __expf(v0); v1 = __expf(v1);
                v2 = __expf(v2); v3 = __expf(v3);
                sum0 += v0 + v1; sum1 += v2 + v3;
            }
            if (MODE & F_OUTF32){
                *(float2*)&Cf[o0] = make_float2(v0, v1);
                *(float2*)&Cf[o1] = make_float2(v2, v3);
            } else {
                *(uint32_t*)&Ch[o0] = pack_h2(v0, v1);
                *(uint32_t*)&Ch[o1] = pack_h2(v2, v3);
            }
        }
        if (MODE & F_EXP){
            sum0 += __shfl_xor_sync(0xffffffffu, sum0, 1);
            sum0 += __shfl_xor_sync(0xffffffffu, sum0, 2);
            sum1 += __shfl_xor_sync(0xffffffffu, sum1, 1);
            sum1 += __shfl_xor_sync(0xffffffffu, sum1, 2);
            if ((lane & 3) == 0){
                atomicAdd(&rsum[r0], sum0);
                atomicAdd(&rsum[r1], sum1);
            }
        }
    }
}

#define MODE_PLAIN 0
#define MODE_S     (F_BIASN|F_EXP)
#define MODE_AV    (F_RINV)
#define MODE_OUT   (F_OUTF32|F_RESID|F_BIASM)

// ---------------- p1: fused prologue ----------------
__global__ void __launch_bounds__(256) p1(const float* __restrict__ x, float2* __restrict__ part,
                                          const float* __restrict__ wq, const float* __restrict__ wk,
                                          const float* __restrict__ wv, const float* __restrict__ wo_,
                                          u16* __restrict__ wA, u16* __restrict__ wB,
                                          const float* __restrict__ bq, const float* __restrict__ bv,
                                          const float* __restrict__ bo,
                                          float* __restrict__ u, float* __restrict__ bp,
                                          float* __restrict__ cv, float* __restrict__ rsum)
{
    __shared__ float buf[33*32];
    const int blk = blockIdx.x, tid = threadIdx.x;
    if (blk < 512){
        const float4* xp = (const float4*)(x + (size_t)blk * 16384);
        float s = 0.f, ss = 0.f;
        #pragma unroll 4
        for (int i = tid; i < 4096; i += 256){
            float4 v = xp[i];
            s  += v.x + v.y + v.z + v.w;
            ss += v.x*v.x + v.y*v.y + v.z*v.z + v.w*v.w;
        }
        #pragma unroll
        for (int o = 16; o; o >>= 1){
            s  += __shfl_xor_sync(0xffffffffu, s,  o);
            ss += __shfl_xor_sync(0xffffffffu, ss, o);
        }
        if ((tid & 31) == 0){ buf[tid>>5] = s; buf[8 + (tid>>5)] = ss; }
        __syncthreads();
        if (tid == 0){
            float t = 0.f, t2 = 0.f;
            #pragma unroll
            for (int i = 0; i < 8; i++){ t += buf[i]; t2 += buf[8+i]; }
            part[blk] = make_float2(t, t2);
        }
    } else if (blk < 1536){
        int idx = blk - 512;
        int z = idx >> 8, rem = idx & 255;
        int c0 = (rem & 15) * 32, r0 = (rem >> 4) * 32;
        const float* src = (z==0) ? wq : (z==1) ? wk : (z==2) ? wv : wo_;
        u16* dst = (z==0) ? wA : (z==1) ? wB : (z==2) ? (wB + CC2) : (wA + CC2);
        int tx = tid & 31, ty = tid >> 5;
        if (z < 3){
            #pragma unroll
            for (int i = 0; i < 4; i++)
                buf[(ty + 8*i)*33 + tx] = src[(size_t)(r0 + ty + 8*i)*CC + c0 + tx];
            __syncthreads();
            #pragma unroll
            for (int i = 0; i < 4; i++)
                dst[(size_t)(c0 + ty + 8*i)*CC + r0 + tx] =
                    __half_as_ushort(__float2half_rn(buf[tx*33 + ty + 8*i]));
        } else {
            #pragma unroll
            for (int i = 0; i < 4; i++){
                size_t o = (size_t)(r0 + ty + 8*i)*CC + c0 + tx;
                dst[o] = __half_as_ushort(__float2half_rn(src[o]));
            }
        }
    } else if (blk < 1552){
        int c0 = (blk - 1536) * 32;
        int ty = tid >> 5, tx = tid & 31;
        float s = 0.f;
        #pragma unroll 8
        for (int o = ty; o < CC; o += 8)
            s += wk[(size_t)o * CC + c0 + tx] * bq[o];
        buf[ty*32 + tx] = s;
        __syncthreads();
        if (ty == 0){
            float t = s;
            #pragma unroll
            for (int i = 1; i < 8; i++) t += buf[i*32 + tx];
            u[c0 + tx] = t;
        }
    } else if (blk < 1616){
        int w = tid >> 5, lane = tid & 31;
        int o = (blk - 1552) * 8 + w;
        const float4* wrow = (const float4*)(wo_ + (size_t)o * CC);
        const float4* bv4  = (const float4*)bv;
        float s = 0.f;
        #pragma unroll
        for (int i = 0; i < 4; i++){
            float4 a = wrow[lane + i*32];
            float4 b = bv4[lane + i*32];
            s += a.x*b.x + a.y*b.y + a.z*b.z + a.w*b.w;
        }
        #pragma unroll
        for (int k = 16; k; k >>= 1) s += __shfl_xor_sync(0xffffffffu, s, k);
        if (!lane) bp[o] = bo[o] + s;
    } else {
        int idx = blk - 1616;   // 0..127
        float* dst = (idx < 64) ? cv : rsum;
        dst[(idx & 63) * 256 + tid] = 0.f;
    }
}

// ---------------- GroupNorm apply: 64x64 tile, paired stores; fused cv partial ----------------
__global__ void __launch_bounds__(256) gn_apply_t(const float* __restrict__ x,
                                                  const float2* __restrict__ part,
                                                  const float* __restrict__ gamma,
                                                  const float* __restrict__ beta,
                                                  u16* __restrict__ hT, u16* __restrict__ h,
                                                  const float* __restrict__ u,
                                                  float* __restrict__ cv, float scl)
{
    __shared__ float tile[64][65];
    __shared__ float cvb[4][64];
    int b = blockIdx.z, g = blockIdx.y, l0 = blockIdx.x * 64;
    float t = 0.f, t2 = 0.f;
    #pragma unroll
    for (int i = 0; i < 8; i++){
        float2 p = part[(b*NGRP + g)*8 + i];
        t += p.x; t2 += p.y;
    }
    const float n = (float)(CPG * LLEN);
    float mean = t / n;
    float var  = t2 / n - mean*mean;
    float inv  = rsqrtf(var + 1e-6f);

    const float* xp = x + ((size_t)b*CC + (size_t)g*CPG) * LLEN;
    u16* hb = h + ((size_t)b*CC + (size_t)g*CPG) * LLEN;
    int tid = threadIdx.x;
    #pragma unroll
    for (int i = 0; i < 16; i++){
        int idx = tid + i*256; int c = idx >> 6, l = idx & 63;
        float v = xp[(size_t)c*LLEN + l0 + l];
        tile[c][l] = (v - mean) * inv * gamma[g*CPG + c] + beta[g*CPG + c];
    }
    __syncthreads();
    #pragma unroll
    for (int i = 0; i < 8; i++){
        int idx = tid + i*256; int c = idx >> 5, l = (idx & 31) * 2;
        *(uint32_t*)&hb[(size_t)c*LLEN + l0 + l] = pack_h2(tile[c][l], tile[c][l+1]);
    }
    size_t base = (size_t)b * LLEN * CC + (size_t)g * CPG;
    #pragma unroll
    for (int i = 0; i < 8; i++){
        int idx = tid + i*256; int l = idx >> 5, c = (idx & 31) * 2;
        *(uint32_t*)&hT[base + (size_t)(l0 + l)*CC + c] = pack_h2(tile[c][l], tile[c+1][l]);
    }
    {
        int l = tid & 63, cgrp = tid >> 6;
        float s = 0.f;
        #pragma unroll
        for (int k = 0; k < 16; k++)
            s += tile[cgrp*16 + k][l] * u[g*CPG + cgrp*16 + k];
        cvb[cgrp][l] = s;
    }
    __syncthreads();
    if (tid < 64){
        float s = cvb[0][tid] + cvb[1][tid] + cvb[2][tid] + cvb[3][tid];
        atomicAdd(&cv[b*LLEN + l0 + tid], s * scl);
    }
}

// ---------------- launch ----------------
extern "C" void kernel_launch(void* const* d_in, const int* in_sizes, int n_in,
                              void* d_out, int out_size)
{
    const float* x     = (const float*)d_in[0];
    const float* gamma = (const float*)d_in[1];
    const float* beta  = (const float*)d_in[2];
    const float* wq    = (const float*)d_in[3];
    const float* bq    = (const float*)d_in[4];
    const float* wk    = (const float*)d_in[5];
    // bk cancels inside softmax — unused
    const float* wv    = (const float*)d_in[7];
    const float* bv    = (const float*)d_in[8];
    const float* wo    = (const float*)d_in[9];
    const float* bo    = (const float*)d_in[10];
    float* out = (float*)d_out;

    u16 *hT,*h,*hp,*g,*s,*wA,*wB,*wM;
    float *u, *bp, *cv, *rsum;
    float2 *part;
    cudaGetSymbolAddress((void**)&hT, g_hT);
    cudaGetSymbolAddress((void**)&h,  g_h);
    cudaGetSymbolAddress((void**)&hp, g_hp);
    cudaGetSymbolAddress((void**)&g,  g_g);
    cudaGetSymbolAddress((void**)&s,  g_s);
    cudaGetSymbolAddress((void**)&wA, g_wA);
    cudaGetSymbolAddress((void**)&wB, g_wB);
    cudaGetSymbolAddress((void**)&wM, g_wM);
    cudaGetSymbolAddress((void**)&u,  g_u);
    cudaGetSymbolAddress((void**)&bp, g_bp);
    cudaGetSymbolAddress((void**)&cv, g_cv);
    cudaGetSymbolAddress((void**)&rsum, g_rsum);
    cudaGetSymbolAddress((void**)&part, g_part);

    cudaFuncSetAttribute(hmma_gemm<MODE_PLAIN>, cudaFuncAttributeMaxDynamicSharedMemorySize, DYN_SMEM);
    cudaFuncSetAttribute(hmma_gemm<MODE_S>,     cudaFuncAttributeMaxDynamicSharedMemorySize, DYN_SMEM);
    cudaFuncSetAttribute(hmma_gemm<MODE_AV>,    cudaFuncAttributeMaxDynamicSharedMemorySize, DYN_SMEM);
    cudaFuncSetAttribute(hmma_gemm<MODE_OUT>,   cudaFuncAttributeMaxDynamicSharedMemorySize, DYN_SMEM);

    const long LL = (long)LLEN * LLEN;
    const float scl = 1.0f / sqrtf((float)CC);

    // fused prologue: GN stats | weight convert | u | bp | zero cv,rsum
    p1<<<1744, 256>>>(x, part, wq, wk, wv, wo, wA, wB, bq, bv, bo, u, bp, cv, rsum);
    // {M, Wov} = batched 512x512x512
    hmma_gemm<MODE_PLAIN><<<dim3(4,4,2), 256, DYN_SMEM>>>(wA, wB,
        CC, CC, CC, CC, (long)CC2, (long)CC2, (long)CC2,
        nullptr, wM, nullptr, nullptr, 0L, nullptr, nullptr, nullptr, 0L, 1.f);
    // GN apply + hT/h + cv
    gn_apply_t<<<dim3(LLEN/64, NGRP, BB), 256>>>(x, part, gamma, beta, hT, h, u, cv, scl);

    dim3 blk(256);
    // h'T[j,c] = sum_c' hT[j,c'] M[c,c']       M=2048, N=512, K=512
    hmma_gemm<MODE_PLAIN><<<dim3(4,16,BB), blk, DYN_SMEM>>>(hT, wM,
        CC, CC, CC, CC, (long)CL, 0L, (long)CL,
        nullptr, hp, nullptr, nullptr, 0L, nullptr, nullptr, nullptr, 0L, 1.f);
    // E[i,j] = exp(scl*(hT[i]·h'T[j]) + cv[b][j]); rsum[b][i] += row sums
    hmma_gemm<MODE_S><<<dim3(16,16,BB), blk, DYN_SMEM>>>(hT, hp,
        CC, CC, CC, LLEN, (long)CL, (long)CL, LL,
        nullptr, s, nullptr, cv, (long)LLEN, nullptr, rsum, nullptr, (long)LLEN, scl);
    // gT[i,c] = (1/rsum[b][i]) * sum_j E[i,j] h[c,j]   M=2048, N=512, K=2048
    hmma_gemm<MODE_AV><<<dim3(4,16,BB), blk, DYN_SMEM>>>(s, h,
        LLEN, LLEN, LLEN, CC, LL, (long)CL, (long)CL,
        nullptr, g, nullptr, nullptr, 0L, nullptr, nullptr, rsum, (long)LLEN, 1.f);
    // out[o,l] = x + sum_c' Wov[o,c'] gT[l,c'] + bp[o]   M=512, N=2048, K=512
    hmma_gemm<MODE_OUT><<<dim3(16,4,BB), blk, DYN_SMEM>>>(wM + CC2, g,
        CC, CC, CC, LLEN, 0L, (long)CL, (long)CL,
        out, nullptr, bp, nullptr, 0L, x, nullptr, nullptr, 0L, 1.f);
}

// round 16
// speedup vs baseline: 1.0121x; 1.0121x over previous
#include <cuda_runtime.h>
#include <cuda_bf16.h>
#include <cuda_fp16.h>
#include <cstdint>
#include <math.h>

#define BB 8
#define CC 512
#define LLEN 2048
#define NGRP 8
#define CPG 64
#define CL (CC*LLEN)
#define CC2 (CC*CC)
typedef unsigned short u16;

// ---------------- scratch ----------------
__device__ u16 g_hT[(size_t)BB*CL];          // hT [B][L][C] fp16
__device__ u16 g_h [(size_t)BB*CL];          // h  [B][C][L] fp16
__device__ u16 g_hp[(size_t)BB*CL];          // h'T = (M h)T [B][L][C]
__device__ u16 g_hv[(size_t)BB*CL];          // hv = Wov·h [B][O][L] fp16
__device__ u16 g_s [(size_t)BB*LLEN*LLEN];   // E = exp(S) [B][L][L]
__device__ u16 g_wA[2*CC2];                  // {wqT, wo} fp16
__device__ u16 g_wB[2*CC2];                  // {wkT, wvT} fp16
__device__ u16 g_wM[2*CC2];                  // {M=WqT*Wk, Wov=Wo*Wv} fp16
__device__ float g_u [CC];                   // WkT * bq
__device__ float g_bp[CC];                   // Wo*bv + bo
__device__ float g_cv[BB*LLEN];              // c_j per (b,j), pre-scaled
__device__ float g_rsum[BB*LLEN];            // row sums of exp(S)
__device__ float2 g_part[512];               // GN partial (sum, sumsq)

// ---------------- helpers ----------------
__device__ __forceinline__ uint32_t smem_u32(const void* p){
    uint32_t a;
    asm("{ .reg .u64 t; cvta.to.shared.u64 t, %1; cvt.u32.u64 %0, t; }" : "=r"(a) : "l"(p));
    return a;
}
__device__ __forceinline__ void cp16(uint32_t s, const void* g){
    asm volatile("cp.async.cg.shared.global [%0], [%1], 16;" :: "r"(s), "l"(g));
}
#define CP_COMMIT() asm volatile("cp.async.commit_group;" ::: "memory")
#define CP_WAIT1()  asm volatile("cp.async.wait_group 1;" ::: "memory")
#define CP_WAIT0()  asm volatile("cp.async.wait_group 0;" ::: "memory")

#define LDX4(r0,r1,r2,r3,addr) \
    asm volatile("ldmatrix.sync.aligned.m8n8.x4.shared.b16 {%0,%1,%2,%3}, [%4];" \
        : "=r"(r0), "=r"(r1), "=r"(r2), "=r"(r3) : "r"(addr))

#define MMA_F16(d, a, b) \
    asm volatile("mma.sync.aligned.m16n8k16.row.col.f32.f16.f16.f32 " \
        "{%0,%1,%2,%3}, {%4,%5,%6,%7}, {%8,%9}, {%0,%1,%2,%3};" \
        : "+f"((d)[0]), "+f"((d)[1]), "+f"((d)[2]), "+f"((d)[3]) \
        : "r"((a)[0]), "r"((a)[1]), "r"((a)[2]), "r"((a)[3]), "r"((b)[0]), "r"((b)[1]))

__device__ __forceinline__ uint32_t pack_h2(float v0, float v1){
    __half2 h = __floats2half2_rn(v0, v1);
    return *(uint32_t*)&h;
}

// ---------------- templated fp16 HMMA GEMM (R14 config: 128 thr, warp 64x64, 2 CTA/SM) ----------------
#define F_OUTF32 1
#define F_RESID  4
#define F_BIASN  8
#define F_EXP    16
#define F_RINVN  32
#define F_BIASM  64
#define OFF_A 0
#define OFF_B 16384
#define STG_B 32768
#define NSTAGE 3
#define DYN_SMEM (NSTAGE*STG_B + 128)

template<int MODE>
__global__ void __launch_bounds__(128, 2)
hmma_gemm(const u16* __restrict__ A, const u16* __restrict__ B,
          int K, int lda, int ldb, int ldc, long sA, long sB, long sC,
          float* __restrict__ Cf, u16* __restrict__ Ch,
          const float* __restrict__ biasM, const float* __restrict__ biasN, long sBN,
          const float* __restrict__ resid,
          float* __restrict__ rsum, const float* __restrict__ rinv, long sRow,
          float scale)
{
    extern __shared__ char dsm[];
    const uint32_t sbase = (smem_u32(dsm) + 127u) & ~127u;
    const int tid = threadIdx.x, lane = tid & 31, wid = tid >> 5;
    const int warpM = (wid & 1) * 64, warpN = (wid >> 1) * 64;
    const int bz = blockIdx.z;
    A += (size_t)bz * sA;
    B += (size_t)bz * sB;
    if (MODE & F_OUTF32) Cf += (size_t)bz * sC; else Ch += (size_t)bz * sC;
    if (MODE & F_RESID)  resid += (size_t)bz * sC;
    if (MODE & F_BIASN)  biasN += (size_t)bz * sBN;
    if (MODE & F_EXP)    rsum  += (size_t)bz * sRow;
    if (MODE & F_RINVN)  rinv  += (size_t)bz * sRow;
    const int m0 = blockIdx.y * 128, n0 = blockIdx.x * 128;
    const int niter = K >> 6;

    const int c_row = tid >> 3, c_seg = tid & 7;
    const uint32_t c_cb = (uint32_t)(c_seg * 16);

    auto issue = [&](int kt){
        const int kk = kt * 64;
        const uint32_t sb = sbase + (kt % NSTAGE) * STG_B;
        #pragma unroll
        for (int j = 0; j < 8; j++){
            const int row = c_row + j * 16;
            const uint32_t sw = (uint32_t)((row & 7) << 4);
            cp16(sb + OFF_A + row * 128 + (c_cb ^ sw),
                 A + (size_t)(m0 + row) * lda + kk + c_seg * 8);
        }
        #pragma unroll
        for (int j = 0; j < 8; j++){
            const int row = c_row + j * 16;
            const uint32_t sw = (uint32_t)((row & 7) << 4);
            cp16(sb + OFF_B + row * 128 + (c_cb ^ sw),
                 B + (size_t)(n0 + row) * ldb + kk + c_seg * 8);
        }
        CP_COMMIT();
    };

    float acc[4][8][4];
    #pragma unroll
    for (int i = 0; i < 4; i++)
        #pragma unroll
        for (int j = 0; j < 8; j++)
            #pragma unroll
            for (int t = 0; t < 4; t++) acc[i][j][t] = 0.f;

    const int aRow0 = warpM + (lane & 15);
    const uint32_t aSw = (uint32_t)((aRow0 & 7) << 4);
    const uint32_t aC  = (uint32_t)((lane >> 4) << 4);
    const int bRow0 = warpN + ((lane >> 4) << 3) + (lane & 7);
    const uint32_t bSw = (uint32_t)((bRow0 & 7) << 4);
    const uint32_t bC  = (uint32_t)(((lane >> 3) & 1) << 4);

    issue(0); if (niter > 1) issue(1);

    for (int kt = 0; kt < niter; kt++){
        if (kt + 1 < niter) CP_WAIT1(); else CP_WAIT0();
        __syncthreads();
        if (kt + 2 < niter) issue(kt + 2);
        const uint32_t sb = sbase + (kt % NSTAGE) * STG_B;

        #pragma unroll
        for (int ko = 0; ko < 4; ko++){
            const uint32_t kb = (uint32_t)(ko * 32);
            uint32_t a_f[4][4], b_f[4][4];
            #pragma unroll
            for (int p = 0; p < 4; p++){
                uint32_t bd = sb + OFF_B + (uint32_t)((bRow0 + p*16) * 128) + ((kb + bC) ^ bSw);
                LDX4(b_f[p][0], b_f[p][1], b_f[p][2], b_f[p][3], bd);
            }
            #pragma unroll
            for (int mt = 0; mt < 4; mt++){
                uint32_t ad = sb + OFF_A + (uint32_t)((aRow0 + (mt&1)*16 + (mt>>1)*32) * 128) + ((kb + aC) ^ aSw);
                LDX4(a_f[mt][0], a_f[mt][1], a_f[mt][2], a_f[mt][3], ad);
            }
            #pragma unroll
            for (int mt = 0; mt < 4; mt++)
                #pragma unroll
                for (int nt = 0; nt < 8; nt++)
                    MMA_F16(acc[mt][nt], a_f[mt], &b_f[nt >> 1][(nt & 1) * 2]);
        }
        // no bottom barrier: prefetch distance 2 of 3 stages + top barrier order stage reuse
    }

    // ---- epilogue (compile-time specialized) ----
    #pragma unroll
    for (int mt = 0; mt < 4; mt++){
        const int mrow = (mt&1)*16 + (mt>>1)*32;
        const int r0 = m0 + warpM + mrow + (lane >> 2);
        const int r1 = r0 + 8;
        float bm0 = 0.f, bm1 = 0.f;
        if (MODE & F_BIASM){ bm0 = biasM[r0]; bm1 = biasM[r1]; }
        float sum0 = 0.f, sum1 = 0.f;
        #pragma unroll
        for (int nt = 0; nt < 8; nt++){
            const int c = n0 + warpN + nt * 8 + ((lane & 3) << 1);
            float v0 = acc[mt][nt][0] * scale;
            float v1 = acc[mt][nt][1] * scale;
            float v2 = acc[mt][nt][2] * scale;
            float v3 = acc[mt][nt][3] * scale;
            if (MODE & F_RINVN){
                float2 rv = *(const float2*)&rinv[c];
                float i0 = 1.f / rv.x, i1 = 1.f / rv.y;
                v0 *= i0; v1 *= i1; v2 *= i0; v3 *= i1;
            }
            v0 += bm0; v1 += bm0; v2 += bm1; v3 += bm1;
            if (MODE & F_BIASN){
                float2 bn = *(const float2*)&biasN[c];
                v0 += bn.x; v1 += bn.y; v2 += bn.x; v3 += bn.y;
            }
            const size_t o0 = (size_t)r0 * ldc + c;
            const size_t o1 = (size_t)r1 * ldc + c;
            if (MODE & F_RESID){
                float2 x0 = *(const float2*)&resid[o0];
                float2 x1 = *(const float2*)&resid[o1];
                v0 += x0.x; v1 += x0.y; v2 += x1.x; v3 += x1.y;
            }
            if (MODE & F_EXP){
                v0 = __expf(v0); v1 = __expf(v1);
                v2 = __expf(v2); v3 = __expf(v3);
                sum0 += v0 + v1; sum1 += v2 + v3;
            }
            if (MODE & F_OUTF32){
                *(float2*)&Cf[o0] = make_float2(v0, v1);
                *(float2*)&Cf[o1] = make_float2(v2, v3);
            } else {
                *(uint32_t*)&Ch[o0] = pack_h2(v0, v1);
                *(uint32_t*)&Ch[o1] = pack_h2(v2, v3);
            }
        }
        if (MODE & F_EXP){
            sum0 += __shfl_xor_sync(0xffffffffu, sum0, 1);
            sum0 += __shfl_xor_sync(0xffffffffu, sum0, 2);
            sum1 += __shfl_xor_sync(0xffffffffu, sum1, 1);
            sum1 += __shfl_xor_sync(0xffffffffu, sum1, 2);
            if ((lane & 3) == 0){
                atomicAdd(&rsum[r0], sum0);
                atomicAdd(&rsum[r1], sum1);
            }
        }
    }
}

#define MODE_PLAIN 0
#define MODE_S     (F_BIASN|F_EXP)
#define MODE_OUT   (F_OUTF32|F_RESID|F_BIASM|F_RINVN)

// ---------------- p1: fused prologue ----------------
__global__ void __launch_bounds__(256) p1(const float* __restrict__ x, float2* __restrict__ part,
                                          const float* __restrict__ wq, const float* __restrict__ wk,
                                          const float* __restrict__ wv, const float* __restrict__ wo_,
                                          u16* __restrict__ wA, u16* __restrict__ wB,
                                          const float* __restrict__ bq, const float* __restrict__ bv,
                                          const float* __restrict__ bo,
                                          float* __restrict__ u, float* __restrict__ bp,
                                          float* __restrict__ cv, float* __restrict__ rsum)
{
    __shared__ float buf[33*32];
    const int blk = blockIdx.x, tid = threadIdx.x;
    if (blk < 512){
        const float4* xp = (const float4*)(x + (size_t)blk * 16384);
        float s = 0.f, ss = 0.f;
        #pragma unroll 4
        for (int i = tid; i < 4096; i += 256){
            float4 v = xp[i];
            s  += v.x + v.y + v.z + v.w;
            ss += v.x*v.x + v.y*v.y + v.z*v.z + v.w*v.w;
        }
        #pragma unroll
        for (int o = 16; o; o >>= 1){
            s  += __shfl_xor_sync(0xffffffffu, s,  o);
            ss += __shfl_xor_sync(0xffffffffu, ss, o);
        }
        if ((tid & 31) == 0){ buf[tid>>5] = s; buf[8 + (tid>>5)] = ss; }
        __syncthreads();
        if (tid == 0){
            float t = 0.f, t2 = 0.f;
            #pragma unroll
            for (int i = 0; i < 8; i++){ t += buf[i]; t2 += buf[8+i]; }
            part[blk] = make_float2(t, t2);
        }
    } else if (blk < 1536){
        int idx = blk - 512;
        int z = idx >> 8, rem = idx & 255;
        int c0 = (rem & 15) * 32, r0 = (rem >> 4) * 32;
        const float* src = (z==0) ? wq : (z==1) ? wk : (z==2) ? wv : wo_;
        u16* dst = (z==0) ? wA : (z==1) ? wB : (z==2) ? (wB + CC2) : (wA + CC2);
        int tx = tid & 31, ty = tid >> 5;
        if (z < 3){
            #pragma unroll
            for (int i = 0; i < 4; i++)
                buf[(ty + 8*i)*33 + tx] = src[(size_t)(r0 + ty + 8*i)*CC + c0 + tx];
            __syncthreads();
            #pragma unroll
            for (int i = 0; i < 4; i++)
                dst[(size_t)(c0 + ty + 8*i)*CC + r0 + tx] =
                    __half_as_ushort(__float2half_rn(buf[tx*33 + ty + 8*i]));
        } else {
            #pragma unroll
            for (int i = 0; i < 4; i++){
                size_t o = (size_t)(r0 + ty + 8*i)*CC + c0 + tx;
                dst[o] = __half_as_ushort(__float2half_rn(src[o]));
            }
        }
    } else if (blk < 1552){
        int c0 = (blk - 1536) * 32;
        int ty = tid >> 5, tx = tid & 31;
        float s = 0.f;
        #pragma unroll 8
        for (int o = ty; o < CC; o += 8)
            s += wk[(size_t)o * CC + c0 + tx] * bq[o];
        buf[ty*32 + tx] = s;
        __syncthreads();
        if (ty == 0){
            float t = s;
            #pragma unroll
            for (int i = 1; i < 8; i++) t += buf[i*32 + tx];
            u[c0 + tx] = t;
        }
    } else if (blk < 1616){
        int w = tid >> 5, lane = tid & 31;
        int o = (blk - 1552) * 8 + w;
        const float4* wrow = (const float4*)(wo_ + (size_t)o * CC);
        const float4* bv4  = (const float4*)bv;
        float s = 0.f;
        #pragma unroll
        for (int i = 0; i < 4; i++){
            float4 a = wrow[lane + i*32];
            float4 b = bv4[lane + i*32];
            s += a.x*b.x + a.y*b.y + a.z*b.z + a.w*b.w;
        }
        #pragma unroll
        for (int k = 16; k; k >>= 1) s += __shfl_xor_sync(0xffffffffu, s, k);
        if (!lane) bp[o] = bo[o] + s;
    } else {
        int idx = blk - 1616;   // 0..127
        float* dst = (idx < 64) ? cv : rsum;
        dst[(idx & 63) * 256 + tid] = 0.f;
    }
}

// ---------------- GroupNorm apply: 64x64 tile, paired stores; fused cv partial ----------------
__global__ void __launch_bounds__(256) gn_apply_t(const float* __restrict__ x,
                                                  const float2* __restrict__ part,
                                                  const float* __restrict__ gamma,
                                                  const float* __restrict__ beta,
                                                  u16* __restrict__ hT, u16* __restrict__ h,
                                                  const float* __restrict__ u,
                                                  float* __restrict__ cv, float scl)
{
    __shared__ float tile[64][65];
    __shared__ float cvb[4][64];
    int b = blockIdx.z, g = blockIdx.y, l0 = blockIdx.x * 64;
    float t = 0.f, t2 = 0.f;
    #pragma unroll
    for (int i = 0; i < 8; i++){
        float2 p = part[(b*NGRP + g)*8 + i];
        t += p.x; t2 += p.y;
    }
    const float n = (float)(CPG * LLEN);
    float mean = t / n;
    float var  = t2 / n - mean*mean;
    float inv  = rsqrtf(var + 1e-6f);

    const float* xp = x + ((size_t)b*CC + (size_t)g*CPG) * LLEN;
    u16* hb = h + ((size_t)b*CC + (size_t)g*CPG) * LLEN;
    int tid = threadIdx.x;
    #pragma unroll
    for (int i = 0; i < 16; i++){
        int idx = tid + i*256; int c = idx >> 6, l = idx & 63;
        float v = xp[(size_t)c*LLEN + l0 + l];
        tile[c][l] = (v - mean) * inv * gamma[g*CPG + c] + beta[g*CPG + c];
    }
    __syncthreads();
    #pragma unroll
    for (int i = 0; i < 8; i++){
        int idx = tid + i*256; int c = idx >> 5, l = (idx & 31) * 2;
        *(uint32_t*)&hb[(size_t)c*LLEN + l0 + l] = pack_h2(tile[c][l], tile[c][l+1]);
    }
    size_t base = (size_t)b * LLEN * CC + (size_t)g * CPG;
    #pragma unroll
    for (int i = 0; i < 8; i++){
        int idx = tid + i*256; int l = idx >> 5, c = (idx & 31) * 2;
        *(uint32_t*)&hT[base + (size_t)(l0 + l)*CC + c] = pack_h2(tile[c][l], tile[c+1][l]);
    }
    {
        int l = tid & 63, cgrp = tid >> 6;
        float s = 0.f;
        #pragma unroll
        for (int k = 0; k < 16; k++)
            s += tile[cgrp*16 + k][l] * u[g*CPG + cgrp*16 + k];
        cvb[cgrp][l] = s;
    }
    __syncthreads();
    if (tid < 64){
        float s = cvb[0][tid] + cvb[1][tid] + cvb[2][tid] + cvb[3][tid];
        atomicAdd(&cv[b*LLEN + l0 + tid], s * scl);
    }
}

// ---------------- launch ----------------
extern "C" void kernel_launch(void* const* d_in, const int* in_sizes, int n_in,
                              void* d_out, int out_size)
{
    const float* x     = (const float*)d_in[0];
    const float* gamma = (const float*)d_in[1];
    const float* beta  = (const float*)d_in[2];
    const float* wq    = (const float*)d_in[3];
    const float* bq    = (const float*)d_in[4];
    const float* wk    = (const float*)d_in[5];
    // bk cancels inside softmax — unused
    const float* wv    = (const float*)d_in[7];
    const float* bv    = (const float*)d_in[8];
    const float* wo    = (const float*)d_in[9];
    const float* bo    = (const float*)d_in[10];
    float* out = (float*)d_out;

    u16 *hT,*h,*hp,*hv,*s,*wA,*wB,*wM;
    float *u, *bp, *cv, *rsum;
    float2 *part;
    cudaGetSymbolAddress((void**)&hT, g_hT);
    cudaGetSymbolAddress((void**)&h,  g_h);
    cudaGetSymbolAddress((void**)&hp, g_hp);
    cudaGetSymbolAddress((void**)&hv, g_hv);
    cudaGetSymbolAddress((void**)&s,  g_s);
    cudaGetSymbolAddress((void**)&wA, g_wA);
    cudaGetSymbolAddress((void**)&wB, g_wB);
    cudaGetSymbolAddress((void**)&wM, g_wM);
    cudaGetSymbolAddress((void**)&u,  g_u);
    cudaGetSymbolAddress((void**)&bp, g_bp);
    cudaGetSymbolAddress((void**)&cv, g_cv);
    cudaGetSymbolAddress((void**)&rsum, g_rsum);
    cudaGetSymbolAddress((void**)&part, g_part);

    cudaFuncSetAttribute(hmma_gemm<MODE_PLAIN>, cudaFuncAttributeMaxDynamicSharedMemorySize, DYN_SMEM);
    cudaFuncSetAttribute(hmma_gemm<MODE_S>,     cudaFuncAttributeMaxDynamicSharedMemorySize, DYN_SMEM);
    cudaFuncSetAttribute(hmma_gemm<MODE_OUT>,   cudaFuncAttributeMaxDynamicSharedMemorySize, DYN_SMEM);

    const long LL = (long)LLEN * LLEN;
    const float scl = 1.0f / sqrtf((float)CC);

    // fused prologue: GN stats | weight convert | u | bp | zero cv,rsum
    p1<<<1744, 256>>>(x, part, wq, wk, wv, wo, wA, wB, bq, bv, bo, u, bp, cv, rsum);
    // {M, Wov} = batched 512x512x512
    hmma_gemm<MODE_PLAIN><<<dim3(4,4,2), 128, DYN_SMEM>>>(wA, wB,
        CC, CC, CC, CC, (long)CC2, (long)CC2, (long)CC2,
        nullptr, wM, nullptr, nullptr, 0L, nullptr, nullptr, nullptr, 0L, 1.f);
    // GN apply + hT/h + cv
    gn_apply_t<<<dim3(LLEN/64, NGRP, BB), 256>>>(x, part, gamma, beta, hT, h, u, cv, scl);

    dim3 blk(128);
    // h'T[j,c] = sum_c' hT[j,c'] M[c,c']       M=2048, N=512, K=512
    hmma_gemm<MODE_PLAIN><<<dim3(4,16,BB), blk, DYN_SMEM>>>(hT, wM,
        CC, CC, CC, CC, (long)CL, 0L, (long)CL,
        nullptr, hp, nullptr, nullptr, 0L, nullptr, nullptr, nullptr, 0L, 1.f);
    // hv[o,j] = sum_c Wov[o,c] hT[j,c]          M=512, N=2048, K=512
    hmma_gemm<MODE_PLAIN><<<dim3(16,4,BB), blk, DYN_SMEM>>>(wM + CC2, hT,
        CC, CC, CC, LLEN, 0L, (long)CL, (long)CL,
        nullptr, hv, nullptr, nullptr, 0L, nullptr, nullptr, nullptr, 0L, 1.f);
    // E[i,j] = exp(scl*(hT[i]·h'T[j]) + cv[b][j]); rsum[b][i] += row sums
    hmma_gemm<MODE_S><<<dim3(16,16,BB), blk, DYN_SMEM>>>(hT, hp,
        CC, CC, CC, LLEN, (long)CL, (long)CL, LL,
        nullptr, s, nullptr, cv, (long)LLEN, nullptr, rsum, nullptr, (long)LLEN, scl);
    // out[o,l] = x + bp[o] + (1/rsum[b][l]) * sum_j hv[o,j] E[l,j]   M=512, N=2048, K=2048
    hmma_gemm<MODE_OUT><<<dim3(16,4,BB), blk, DYN_SMEM>>>(hv, s,
        LLEN, LLEN, LLEN, LLEN, (long)CL, LL, (long)CL,
        out, nullptr, bp, nullptr, 0L, x, nullptr, rsum, (long)LLEN, 1.f);
}

// round 17
// speedup vs baseline: 1.0475x; 1.0349x over previous
#include <cuda_runtime.h>
#include <cuda_bf16.h>
#include <cuda_fp16.h>
#include <cstdint>
#include <math.h>

#define BB 8
#define CC 512
#define LLEN 2048
#define NGRP 8
#define CPG 64
#define CL (CC*LLEN)
#define CC2 (CC*CC)
typedef unsigned short u16;

// ---------------- scratch ----------------
__device__ u16 g_hT[(size_t)BB*CL];          // hT [B][L][C] fp16
__device__ u16 g_h [(size_t)BB*CL];          // h  [B][C][L] fp16
__device__ u16 g_hp[(size_t)BB*CL];          // h'T = (M h)T [B][L][C]
__device__ u16 g_g [(size_t)BB*CL];          // gT = (P h)T [B][L][C]
__device__ u16 g_s [(size_t)BB*LLEN*LLEN];   // E = exp(S) [B][L][L]
__device__ u16 g_wA[2*CC2];                  // {wqT, wo} fp16
__device__ u16 g_wB[2*CC2];                  // {wkT, wvT} fp16
__device__ u16 g_wM[2*CC2];                  // {M=WqT*Wk, Wov=Wo*Wv} fp16
__device__ float g_u [CC];                   // WkT * bq
__device__ float g_bp[CC];                   // Wo*bv + bo
__device__ float g_cv[BB*LLEN];              // c_j per (b,j), pre-scaled
__device__ float g_rsum[BB*LLEN];            // row sums of exp(S)
__device__ float2 g_part[512];               // GN partial (sum, sumsq)

// ---------------- helpers ----------------
__device__ __forceinline__ uint32_t smem_u32(const void* p){
    uint32_t a;
    asm("{ .reg .u64 t; cvta.to.shared.u64 t, %1; cvt.u32.u64 %0, t; }" : "=r"(a) : "l"(p));
    return a;
}
__device__ __forceinline__ void cp16(uint32_t s, const void* g){
    asm volatile("cp.async.cg.shared.global [%0], [%1], 16;" :: "r"(s), "l"(g));
}
#define CP_COMMIT() asm volatile("cp.async.commit_group;" ::: "memory")
#define CP_WAIT1()  asm volatile("cp.async.wait_group 1;" ::: "memory")
#define CP_WAIT0()  asm volatile("cp.async.wait_group 0;" ::: "memory")

#define LDX4(r0,r1,r2,r3,addr) \
    asm volatile("ldmatrix.sync.aligned.m8n8.x4.shared.b16 {%0,%1,%2,%3}, [%4];" \
        : "=r"(r0), "=r"(r1), "=r"(r2), "=r"(r3) : "r"(addr))

#define MMA_F16(d, a, b) \
    asm volatile("mma.sync.aligned.m16n8k16.row.col.f32.f16.f16.f32 " \
        "{%0,%1,%2,%3}, {%4,%5,%6,%7}, {%8,%9}, {%0,%1,%2,%3};" \
        : "+f"((d)[0]), "+f"((d)[1]), "+f"((d)[2]), "+f"((d)[3]) \
        : "r"((a)[0]), "r"((a)[1]), "r"((a)[2]), "r"((a)[3]), "r"((b)[0]), "r"((b)[1]))

__device__ __forceinline__ uint32_t pack_h2(float v0, float v1){
    __half2 h = __floats2half2_rn(v0, v1);
    return *(uint32_t*)&h;
}

// ---------------- templated fp16 HMMA GEMM (R14 config; K/lda/ldb compile-time) ----------------
#define F_OUTF32 1
#define F_RESID  4
#define F_BIASN  8
#define F_EXP    16
#define F_RINV   32
#define F_BIASM  64
#define OFF_A 0
#define OFF_B 16384
#define STG_B 32768
#define NSTAGE 3
#define DYN_SMEM (NSTAGE*STG_B + 128)

template<int MODE, int KD, int LDA, int LDB>
__global__ void __launch_bounds__(128, 2)
hmma_gemm(const u16* __restrict__ A, const u16* __restrict__ B,
          int ldc, long sA, long sB, long sC,
          float* __restrict__ Cf, u16* __restrict__ Ch,
          const float* __restrict__ biasM, const float* __restrict__ biasN, long sBN,
          const float* __restrict__ resid,
          float* __restrict__ rsum, const float* __restrict__ rinv, long sRow,
          float scale)
{
    extern __shared__ char dsm[];
    const uint32_t sbase = (smem_u32(dsm) + 127u) & ~127u;
    const int tid = threadIdx.x, lane = tid & 31, wid = tid >> 5;
    const int warpM = (wid & 1) * 64, warpN = (wid >> 1) * 64;
    const int bz = blockIdx.z;
    A += (size_t)bz * sA;
    B += (size_t)bz * sB;
    if (MODE & F_OUTF32) Cf += (size_t)bz * sC; else Ch += (size_t)bz * sC;
    if (MODE & F_RESID)  resid += (size_t)bz * sC;
    if (MODE & F_BIASN)  biasN += (size_t)bz * sBN;
    if (MODE & F_EXP)    rsum  += (size_t)bz * sRow;
    if (MODE & F_RINV)   rinv  += (size_t)bz * sRow;
    const int m0 = blockIdx.y * 128, n0 = blockIdx.x * 128;
    constexpr int niter = KD >> 6;

    const int c_row = tid >> 3, c_seg = tid & 7;
    const uint32_t c_cb = (uint32_t)(c_seg * 16);

    auto issue = [&](int kt){
        const int kk = kt * 64;
        const uint32_t sb = sbase + (kt % NSTAGE) * STG_B;
        #pragma unroll
        for (int j = 0; j < 8; j++){
            const int row = c_row + j * 16;
            const uint32_t sw = (uint32_t)((row & 7) << 4);
            cp16(sb + OFF_A + row * 128 + (c_cb ^ sw),
                 A + (size_t)(m0 + row) * LDA + kk + c_seg * 8);
        }
        #pragma unroll
        for (int j = 0; j < 8; j++){
            const int row = c_row + j * 16;
            const uint32_t sw = (uint32_t)((row & 7) << 4);
            cp16(sb + OFF_B + row * 128 + (c_cb ^ sw),
                 B + (size_t)(n0 + row) * LDB + kk + c_seg * 8);
        }
        CP_COMMIT();
    };

    float acc[4][8][4];
    #pragma unroll
    for (int i = 0; i < 4; i++)
        #pragma unroll
        for (int j = 0; j < 8; j++)
            #pragma unroll
            for (int t = 0; t < 4; t++) acc[i][j][t] = 0.f;

    const int aRow0 = warpM + (lane & 15);
    const uint32_t aSw = (uint32_t)((aRow0 & 7) << 4);
    const uint32_t aC  = (uint32_t)((lane >> 4) << 4);
    const int bRow0 = warpN + ((lane >> 4) << 3) + (lane & 7);
    const uint32_t bSw = (uint32_t)((bRow0 & 7) << 4);
    const uint32_t bC  = (uint32_t)(((lane >> 3) & 1) << 4);

    issue(0); if (niter > 1) issue(1);

    for (int kt = 0; kt < niter; kt++){
        if (kt + 1 < niter) CP_WAIT1(); else CP_WAIT0();
        __syncthreads();
        if (kt + 2 < niter) issue(kt + 2);
        const uint32_t sb = sbase + (kt % NSTAGE) * STG_B;

        #pragma unroll
        for (int ko = 0; ko < 4; ko++){
            const uint32_t kb = (uint32_t)(ko * 32);
            uint32_t a_f[4][4], b_f[4][4];
            #pragma unroll
            for (int p = 0; p < 4; p++){
                uint32_t bd = sb + OFF_B + (uint32_t)((bRow0 + p*16) * 128) + ((kb + bC) ^ bSw);
                LDX4(b_f[p][0], b_f[p][1], b_f[p][2], b_f[p][3], bd);
            }
            #pragma unroll
            for (int mt = 0; mt < 4; mt++){
                uint32_t ad = sb + OFF_A + (uint32_t)((aRow0 + (mt&1)*16 + (mt>>1)*32) * 128) + ((kb + aC) ^ aSw);
                LDX4(a_f[mt][0], a_f[mt][1], a_f[mt][2], a_f[mt][3], ad);
            }
            #pragma unroll
            for (int mt = 0; mt < 4; mt++)
                #pragma unroll
                for (int nt = 0; nt < 8; nt++)
                    MMA_F16(acc[mt][nt], a_f[mt], &b_f[nt >> 1][(nt & 1) * 2]);
        }
        // no bottom barrier: prefetch distance 2 of 3 stages + top barrier order stage reuse
    }

    // ---- epilogue (compile-time specialized) ----
    #pragma unroll
    for (int mt = 0; mt < 4; mt++){
        const int mrow = (mt&1)*16 + (mt>>1)*32;
        const int r0 = m0 + warpM + mrow + (lane >> 2);
        const int r1 = r0 + 8;
        float bm0 = 0.f, bm1 = 0.f;
        if (MODE & F_BIASM){ bm0 = biasM[r0]; bm1 = biasM[r1]; }
        float sc0 = 1.f, sc1 = 1.f;
        if (MODE & F_RINV){ sc0 = 1.f / rinv[r0]; sc1 = 1.f / rinv[r1]; }
        float sum0 = 0.f, sum1 = 0.f;
        #pragma unroll
        for (int nt = 0; nt < 8; nt++){
            const int c = n0 + warpN + nt * 8 + ((lane & 3) << 1);
            float v0 = acc[mt][nt][0] * scale + bm0;
            float v1 = acc[mt][nt][1] * scale + bm0;
            float v2 = acc[mt][nt][2] * scale + bm1;
            float v3 = acc[mt][nt][3] * scale + bm1;
            if (MODE & F_RINV){ v0 *= sc0; v1 *= sc0; v2 *= sc1; v3 *= sc1; }
            if (MODE & F_BIASN){
                float2 bn = *(const float2*)&biasN[c];
                v0 += bn.x; v1 += bn.y; v2 += bn.x; v3 += bn.y;
            }
            const size_t o0 = (size_t)r0 * ldc + c;
            const size_t o1 = (size_t)r1 * ldc + c;
            if (MODE & F_RESID){
                float2 x0 = *(const float2*)&resid[o0];
                float2 x1 = *(const float2*)&resid[o1];
                v0 += x0.x; v1 += x0.y; v2 += x1.x; v3 += x1.y;
            }
            if (MODE & F_EXP){
                v0 = __expf(v0); v1 = __expf(v1);
                v2 = __expf(v2); v3 = __expf(v3);
                sum0 += v0 + v1; sum1 += v2 + v3;
            }
            if (MODE & F_OUTF32){
                *(float2*)&Cf[o0] = make_float2(v0, v1);
                *(float2*)&Cf[o1] = make_float2(v2, v3);
            } else {
                *(uint32_t*)&Ch[o0] = pack_h2(v0, v1);
                *(uint32_t*)&Ch[o1] = pack_h2(v2, v3);
            }
        }
        if (MODE & F_EXP){
            sum0 += __shfl_xor_sync(0xffffffffu, sum0, 1);
            sum0 += __shfl_xor_sync(0xffffffffu, sum0, 2);
            sum1 += __shfl_xor_sync(0xffffffffu, sum1, 1);
            sum1 += __shfl_xor_sync(0xffffffffu, sum1, 2);
            if ((lane & 3) == 0){
                atomicAdd(&rsum[r0], sum0);
                atomicAdd(&rsum[r1], sum1);
            }
        }
    }
}

#define MODE_PLAIN 0
#define MODE_S     (F_BIASN|F_EXP)
#define MODE_AV    (F_RINV)
#define MODE_OUT   (F_OUTF32|F_RESID|F_BIASM)

// ---------------- p1: fused prologue ----------------
__global__ void __launch_bounds__(256) p1(const float* __restrict__ x, float2* __restrict__ part,
                                          const float* __restrict__ wq, const float* __restrict__ wk,
                                          const float* __restrict__ wv, const float* __restrict__ wo_,
                                          u16* __restrict__ wA, u16* __restrict__ wB,
                                          const float* __restrict__ bq, const float* __restrict__ bv,
                                          const float* __restrict__ bo,
                                          float* __restrict__ u, float* __restrict__ bp,
                                          float* __restrict__ cv, float* __restrict__ rsum)
{
    __shared__ float buf[33*32];
    const int blk = blockIdx.x, tid = threadIdx.x;
    if (blk < 512){
        const float4* xp = (const float4*)(x + (size_t)blk * 16384);
        float s = 0.f, ss = 0.f;
        #pragma unroll 4
        for (int i = tid; i < 4096; i += 256){
            float4 v = xp[i];
            s  += v.x + v.y + v.z + v.w;
            ss += v.x*v.x + v.y*v.y + v.z*v.z + v.w*v.w;
        }
        #pragma unroll
        for (int o = 16; o; o >>= 1){
            s  += __shfl_xor_sync(0xffffffffu, s,  o);
            ss += __shfl_xor_sync(0xffffffffu, ss, o);
        }
        if ((tid & 31) == 0){ buf[tid>>5] = s; buf[8 + (tid>>5)] = ss; }
        __syncthreads();
        if (tid == 0){
            float t = 0.f, t2 = 0.f;
            #pragma unroll
            for (int i = 0; i < 8; i++){ t += buf[i]; t2 += buf[8+i]; }
            part[blk] = make_float2(t, t2);
        }
    } else if (blk < 1536){
        int idx = blk - 512;
        int z = idx >> 8, rem = idx & 255;
        int c0 = (rem & 15) * 32, r0 = (rem >> 4) * 32;
        const float* src = (z==0) ? wq : (z==1) ? wk : (z==2) ? wv : wo_;
        u16* dst = (z==0) ? wA : (z==1) ? wB : (z==2) ? (wB + CC2) : (wA + CC2);
        int tx = tid & 31, ty = tid >> 5;
        if (z < 3){
            #pragma unroll
            for (int i = 0; i < 4; i++)
                buf[(ty + 8*i)*33 + tx] = src[(size_t)(r0 + ty + 8*i)*CC + c0 + tx];
            __syncthreads();
            #pragma unroll
            for (int i = 0; i < 4; i++)
                dst[(size_t)(c0 + ty + 8*i)*CC + r0 + tx] =
                    __half_as_ushort(__float2half_rn(buf[tx*33 + ty + 8*i]));
        } else {
            #pragma unroll
            for (int i = 0; i < 4; i++){
                size_t o = (size_t)(r0 + ty + 8*i)*CC + c0 + tx;
                dst[o] = __half_as_ushort(__float2half_rn(src[o]));
            }
        }
    } else if (blk < 1552){
        int c0 = (blk - 1536) * 32;
        int ty = tid >> 5, tx = tid & 31;
        float s = 0.f;
        #pragma unroll 8
        for (int o = ty; o < CC; o += 8)
            s += wk[(size_t)o * CC + c0 + tx] * bq[o];
        buf[ty*32 + tx] = s;
        __syncthreads();
        if (ty == 0){
            float t = s;
            #pragma unroll
            for (int i = 1; i < 8; i++) t += buf[i*32 + tx];
            u[c0 + tx] = t;
        }
    } else if (blk < 1616){
        int w = tid >> 5, lane = tid & 31;
        int o = (blk - 1552) * 8 + w;
        const float4* wrow = (const float4*)(wo_ + (size_t)o * CC);
        const float4* bv4  = (const float4*)bv;
        float s = 0.f;
        #pragma unroll
        for (int i = 0; i < 4; i++){
            float4 a = wrow[lane + i*32];
            float4 b = bv4[lane + i*32];
            s += a.x*b.x + a.y*b.y + a.z*b.z + a.w*b.w;
        }
        #pragma unroll
        for (int k = 16; k; k >>= 1) s += __shfl_xor_sync(0xffffffffu, s, k);
        if (!lane) bp[o] = bo[o] + s;
    } else {
        int idx = blk - 1616;   // 0..127
        float* dst = (idx < 64) ? cv : rsum;
        dst[(idx & 63) * 256 + tid] = 0.f;
    }
}

// ---------------- GroupNorm apply: 64x64 tile, paired stores; fused cv partial ----------------
__global__ void __launch_bounds__(256) gn_apply_t(const float* __restrict__ x,
                                                  const float2* __restrict__ part,
                                                  const float* __restrict__ gamma,
                                                  const float* __restrict__ beta,
                                                  u16* __restrict__ hT, u16* __restrict__ h,
                                                  const float* __restrict__ u,
                                                  float* __restrict__ cv, float scl)
{
    __shared__ float tile[64][65];
    __shared__ float cvb[4][64];
    int b = blockIdx.z, g = blockIdx.y, l0 = blockIdx.x * 64;
    float t = 0.f, t2 = 0.f;
    #pragma unroll
    for (int i = 0; i < 8; i++){
        float2 p = part[(b*NGRP + g)*8 + i];
        t += p.x; t2 += p.y;
    }
    const float n = (float)(CPG * LLEN);
    float mean = t / n;
    float var  = t2 / n - mean*mean;
    float inv  = rsqrtf(var + 1e-6f);

    const float* xp = x + ((size_t)b*CC + (size_t)g*CPG) * LLEN;
    u16* hb = h + ((size_t)b*CC + (size_t)g*CPG) * LLEN;
    int tid = threadIdx.x;
    #pragma unroll
    for (int i = 0; i < 16; i++){
        int idx = tid + i*256; int c = idx >> 6, l = idx & 63;
        float v = xp[(size_t)c*LLEN + l0 + l];
        tile[c][l] = (v - mean) * inv * gamma[g*CPG + c] + beta[g*CPG + c];
    }
    __syncthreads();
    #pragma unroll
    for (int i = 0; i < 8; i++){
        int idx = tid + i*256; int c = idx >> 5, l = (idx & 31) * 2;
        *(uint32_t*)&hb[(size_t)c*LLEN + l0 + l] = pack_h2(tile[c][l], tile[c][l+1]);
    }
    size_t base = (size_t)b * LLEN * CC + (size_t)g * CPG;
    #pragma unroll
    for (int i = 0; i < 8; i++){
        int idx = tid + i*256; int l = idx >> 5, c = (idx & 31) * 2;
        *(uint32_t*)&hT[base + (size_t)(l0 + l)*CC + c] = pack_h2(tile[c][l], tile[c+1][l]);
    }
    {
        int l = tid & 63, cgrp = tid >> 6;
        float s = 0.f;
        #pragma unroll
        for (int k = 0; k < 16; k++)
            s += tile[cgrp*16 + k][l] * u[g*CPG + cgrp*16 + k];
        cvb[cgrp][l] = s;
    }
    __syncthreads();
    if (tid < 64){
        float s = cvb[0][tid] + cvb[1][tid] + cvb[2][tid] + cvb[3][tid];
        atomicAdd(&cv[b*LLEN + l0 + tid], s * scl);
    }
}

// ---------------- launch ----------------
extern "C" void kernel_launch(void* const* d_in, const int* in_sizes, int n_in,
                              void* d_out, int out_size)
{
    const float* x     = (const float*)d_in[0];
    const float* gamma = (const float*)d_in[1];
    const float* beta  = (const float*)d_in[2];
    const float* wq    = (const float*)d_in[3];
    const float* bq    = (const float*)d_in[4];
    const float* wk    = (const float*)d_in[5];
    // bk cancels inside softmax — unused
    const float* wv    = (const float*)d_in[7];
    const float* bv    = (const float*)d_in[8];
    const float* wo    = (const float*)d_in[9];
    const float* bo    = (const float*)d_in[10];
    float* out = (float*)d_out;

    u16 *hT,*h,*hp,*g,*s,*wA,*wB,*wM;
    float *u, *bp, *cv, *rsum;
    float2 *part;
    cudaGetSymbolAddress((void**)&hT, g_hT);
    cudaGetSymbolAddress((void**)&h,  g_h);
    cudaGetSymbolAddress((void**)&hp, g_hp);
    cudaGetSymbolAddress((void**)&g,  g_g);
    cudaGetSymbolAddress((void**)&s,  g_s);
    cudaGetSymbolAddress((void**)&wA, g_wA);
    cudaGetSymbolAddress((void**)&wB, g_wB);
    cudaGetSymbolAddress((void**)&wM, g_wM);
    cudaGetSymbolAddress((void**)&u,  g_u);
    cudaGetSymbolAddress((void**)&bp, g_bp);
    cudaGetSymbolAddress((void**)&cv, g_cv);
    cudaGetSymbolAddress((void**)&rsum, g_rsum);
    cudaGetSymbolAddress((void**)&part, g_part);

    cudaFuncSetAttribute(hmma_gemm<MODE_PLAIN,512,512,512>,   cudaFuncAttributeMaxDynamicSharedMemorySize, DYN_SMEM);
    cudaFuncSetAttribute(hmma_gemm<MODE_S,512,512,512>,       cudaFuncAttributeMaxDynamicSharedMemorySize, DYN_SMEM);
    cudaFuncSetAttribute(hmma_gemm<MODE_AV,2048,2048,2048>,   cudaFuncAttributeMaxDynamicSharedMemorySize, DYN_SMEM);
    cudaFuncSetAttribute(hmma_gemm<MODE_OUT,512,512,512>,     cudaFuncAttributeMaxDynamicSharedMemorySize, DYN_SMEM);

    const long LL = (long)LLEN * LLEN;
    const float scl = 1.0f / sqrtf((float)CC);

    // fused prologue: GN stats | weight convert | u | bp | zero cv,rsum
    p1<<<1744, 256>>>(x, part, wq, wk, wv, wo, wA, wB, bq, bv, bo, u, bp, cv, rsum);
    // {M, Wov} = batched 512x512x512
    hmma_gemm<MODE_PLAIN,512,512,512><<<dim3(4,4,2), 128, DYN_SMEM>>>(wA, wB,
        CC, (long)CC2, (long)CC2, (long)CC2,
        nullptr, wM, nullptr, nullptr, 0L, nullptr, nullptr, nullptr, 0L, 1.f);
    // GN apply + hT/h + cv
    gn_apply_t<<<dim3(LLEN/64, NGRP, BB), 256>>>(x, part, gamma, beta, hT, h, u, cv, scl);

    dim3 blk(128);
    // h'T[j,c] = sum_c' hT[j,c'] M[c,c']       M=2048, N=512, K=512
    hmma_gemm<MODE_PLAIN,512,512,512><<<dim3(4,16,BB), blk, DYN_SMEM>>>(hT, wM,
        CC, (long)CL, 0L, (long)CL,
        nullptr, hp, nullptr, nullptr, 0L, nullptr, nullptr, nullptr, 0L, 1.f);
    // E[i,j] = exp(scl*(hT[i]·h'T[j]) + cv[b][j]); rsum[b][i] += row sums
    hmma_gemm<MODE_S,512,512,512><<<dim3(16,16,BB), blk, DYN_SMEM>>>(hT, hp,
        LLEN, (long)CL, (long)CL, LL,
        nullptr, s, nullptr, cv, (long)LLEN, nullptr, rsum, nullptr, (long)LLEN, scl);
    // gT[i,c] = (1/rsum[b][i]) * sum_j E[i,j] h[c,j]   M=2048, N=512, K=2048
    hmma_gemm<MODE_AV,2048,2048,2048><<<dim3(4,16,BB), blk, DYN_SMEM>>>(s, h,
        CC, LL, (long)CL, (long)CL,
        nullptr, g, nullptr, nullptr, 0L, nullptr, nullptr, rsum, (long)LLEN, 1.f);
    // out[o,l] = x + sum_c' Wov[o,c'] gT[l,c'] + bp[o]   M=512, N=2048, K=512
    hmma_gemm<MODE_OUT,512,512,512><<<dim3(16,4,BB), blk, DYN_SMEM>>>(wM + CC2, g,
        LLEN, 0L, (long)CL, (long)CL,
        out, nullptr, bp, nullptr, 0L, x, nullptr, nullptr, 0L, 1.f);
}